// round 1
// baseline (speedup 1.0000x reference)
#include <cuda_runtime.h>

// CRF NLL: B=1024, T=512, K=64, START=62, STOP=63, NEG=-10000
// Strategy: exp-domain forward recursion.
//   carry v[j] = exp(alpha[j] - M), M = ktot*ln2 (power-of-2 rescaling only)
//   step:  v'[i] = (sum_j Et[i,j] * v[j]) * exp(emit[i]) * 2^-k
//   with Et = exp(transitions) precomputed in registers (row per thread).
// One block per batch element, 64 threads (thread i owns output tag i).
// Gold score folded into the same loop. Final: atomicAdd of (fwd-gold)/B.

#define B_ 1024
#define T_ 512
#define K_ 64
#define START_ 62
#define STOP_ 63

__global__ void crf_zero_kernel(float* out) { out[0] = 0.0f; }

__global__ __launch_bounds__(64) void crf_fwd_kernel(
    const float* __restrict__ feats,      // [B,T,K] f32
    const int*   __restrict__ lengths,    // [B] i32
    const int*   __restrict__ tags,       // [B,T] i32
    const float* __restrict__ trans,      // [K,K] f32  trans[next, prev]
    float* __restrict__ out)              // [1] f32
{
    __shared__ float4 vbuf[2][16];        // double-buffered v[64]
    __shared__ float partu[2], partg[2];

    const int i = threadIdx.x;            // current-tag index this thread owns
    const int b = blockIdx.x;
    const int len = lengths[b];

    // Et[i][j] = exp(trans[i,j]); row i register-resident.
    float Et[64];
#pragma unroll
    for (int j = 0; j < 64; ++j) Et[j] = __expf(trans[i * 64 + j]);
    const float EtStop = __expf(trans[STOP_ * 64 + i]);

    // v0: exp(alpha0 - 0) -> 1 at START, 0 elsewhere (exp(-10000) underflows
    // to exactly 0 in the reference's own fp32 logsumexp too).
    ((float*)vbuf[0])[i] = (i == START_) ? 1.0f : 0.0f;

    const float* fb = feats + (size_t)b * (T_ * K_);
    const int*   tb = tags  + (size_t)b * T_;

    float emit = fb[i];                   // prefetch t=0
    int   tag  = tb[0];
    __syncthreads();

    float gold = 0.0f;
    int prevtag = START_;
    int ktot = 0;                         // accumulated binary exponent of scale
    int cur = 0;

    for (int t = 0; t < len; ++t) {
        // prefetch next step's emission + tag (hide DRAM latency behind dot)
        float emit_n = 0.0f; int tag_n = 0;
        if (t + 1 < len) {
            emit_n = fb[(t + 1) * K_ + i];
            tag_n  = tb[t + 1];
        }

        const float4* vv = (const float4*)vbuf[cur];
        float s0 = 0.f, s1 = 0.f, s2 = 0.f, s3 = 0.f;
        float mx = 0.0f;
        const bool doR = ((t & 3) == 3);  // rescale every 4 steps
#pragma unroll
        for (int q = 0; q < 16; ++q) {
            float4 x = vv[q];             // broadcast LDS.128, conflict-free
            s0 = fmaf(Et[4 * q + 0], x.x, s0);
            s1 = fmaf(Et[4 * q + 1], x.y, s1);
            s2 = fmaf(Et[4 * q + 2], x.z, s2);
            s3 = fmaf(Et[4 * q + 3], x.w, s3);
            if (doR)
                mx = fmaxf(mx, fmaxf(fmaxf(x.x, x.y), fmaxf(x.z, x.w)));
        }
        float S = (s0 + s1) + (s2 + s3);
        float w = S * __expf(emit);

        if (doR && mx > 0.0f) {
            // All threads computed identical mx from identical shared data,
            // so k (and ktot) stay consistent with zero communication.
            int k = ((__float_as_int(mx) >> 23) & 0xFF) - 127;
            ktot += k;
            w *= __int_as_float((127 - k) << 23);  // * 2^-k
        }

        // gold score: emission term (owner thread) + transition term (thread 0)
        if (i == tag) gold += emit;
        if (i == 0)   gold += trans[tag * 64 + prevtag];
        prevtag = tag;

        cur ^= 1;
        ((float*)vbuf[cur])[i] = w;
        emit = emit_n;
        tag  = tag_n;
        __syncthreads();
    }

    // terminal transition into STOP (the t == len term of the gold trans sum)
    if (i == 0) gold += trans[STOP_ * 64 + prevtag];

    // forward = M + log( sum_i v[i] * exp(trans[STOP, i]) )
    float u = ((float*)vbuf[cur])[i] * EtStop;

#pragma unroll
    for (int off = 16; off; off >>= 1) {
        u    += __shfl_xor_sync(0xFFFFFFFFu, u,    off);
        gold += __shfl_xor_sync(0xFFFFFFFFu, gold, off);
    }
    if ((i & 31) == 0) { partu[i >> 5] = u; partg[i >> 5] = gold; }
    __syncthreads();
    if (i == 0) {
        float usum = partu[0] + partu[1];
        float g    = partg[0] + partg[1];
        float fwd  = (float)((double)ktot * 0.69314718055994530942) + logf(usum);
        atomicAdd(out, (fwd - g) * (1.0f / (float)B_));
    }
}

extern "C" void kernel_launch(void* const* d_in, const int* in_sizes, int n_in,
                              void* d_out, int out_size)
{
    const float* feats   = (const float*)d_in[0];
    const int*   lengths = (const int*)  d_in[1];
    const int*   tags    = (const int*)  d_in[2];
    const float* trans   = (const float*)d_in[3];
    float* out = (float*)d_out;

    crf_zero_kernel<<<1, 1>>>(out);
    crf_fwd_kernel<<<B_, 64>>>(feats, lengths, tags, trans, out);
}

// round 2
// speedup vs baseline: 1.8128x; 1.8128x over previous
#include <cuda_runtime.h>

// CRF NLL: B=1024, T=512, K=64, START=62, STOP=63
// Exp-domain forward recursion, one block (64 threads) per batch element.
//   v[j] = exp(alpha[j] - ktot*ln2);  v' = (Et @ v) .* exp(emit) .* 2^-k
// Et = exp(trans) row-resident per thread, packed f32x2 pairs.
// Emissions prefetched 8 steps ahead (2 groups of 4). Gold score computed
// in a fully parallel prologue. Single __syncthreads per step.

#define B_ 1024
#define T_ 512
#define K_ 64
#define START_ 62
#define STOP_ 63

typedef unsigned long long u64;

__device__ __forceinline__ u64 fma2(u64 a, u64 b, u64 c) {
    u64 d;
    asm("fma.rn.f32x2 %0, %1, %2, %3;" : "=l"(d) : "l"(a), "l"(b), "l"(c));
    return d;
}
__device__ __forceinline__ u64 add2(u64 a, u64 b) {
    u64 d;
    asm("add.rn.f32x2 %0, %1, %2;" : "=l"(d) : "l"(a), "l"(b));
    return d;
}
__device__ __forceinline__ u64 pack2(float lo, float hi) {
    u64 d;
    asm("mov.b64 %0, {%1, %2};" : "=l"(d) : "f"(lo), "f"(hi));
    return d;
}
__device__ __forceinline__ float sum2(u64 a) {
    float lo, hi;
    asm("mov.b64 {%0, %1}, %2;" : "=f"(lo), "=f"(hi) : "l"(a));
    return lo + hi;
}

__global__ void crf_zero_kernel(float* out) { out[0] = 0.0f; }

__global__ __launch_bounds__(64, 8) void crf_fwd_kernel(
    const float* __restrict__ feats,      // [B,T,K]
    const int*   __restrict__ lengths,    // [B]
    const int*   __restrict__ tags,       // [B,T]
    const float* __restrict__ trans,      // [K,K]  trans[next, prev]
    float* __restrict__ out)
{
    __shared__ __align__(16) float vbuf[2][64];
    __shared__ float partu[2], partg[2];

    const int i = threadIdx.x;
    const int b = blockIdx.x;
    const int len = lengths[b];

    const float* fb = feats + (size_t)b * (T_ * K_);
    const int*   tb = tags  + (size_t)b * T_;

    // ---- gold score, fully parallel over t (out of the serial loop) ----
    float gold = 0.0f;
#pragma unroll
    for (int r = 0; r < 8; ++r) {
        int t = i + 64 * r;
        if (t < len) {
            int tg = tb[t];
            int pv = t ? tb[t - 1] : START_;
            gold += fb[t * K_ + tg] + trans[tg * K_ + pv];
        }
    }
    if (i == 0) gold += trans[STOP_ * K_ + tb[len - 1]];

    // ---- Et row i, packed as f32x2 pairs ----
    u64 Et2[32];
#pragma unroll
    for (int q = 0; q < 32; ++q)
        Et2[q] = pack2(__expf(trans[i * K_ + 2 * q]),
                       __expf(trans[i * K_ + 2 * q + 1]));
    const float EtStop = __expf(trans[STOP_ * K_ + i]);

    vbuf[0][i] = (i == START_) ? 1.0f : 0.0f;

    // ---- emission prefetch rings: cur group (e), next (f), loading (g) ----
    float e0 = fb[0 * K_ + i], e1 = fb[1 * K_ + i],
          e2 = fb[2 * K_ + i], e3 = fb[3 * K_ + i];
    float f0 = fb[4 * K_ + i], f1 = fb[5 * K_ + i],
          f2 = fb[6 * K_ + i], f3 = fb[7 * K_ + i];
    __syncthreads();

    int ktot = 0, cur = 0;
    const int len4 = len & ~3;

    // one forward step, packed f32x2 dot
#define STEP_PACKED(EM)                                                    \
    {                                                                      \
        const ulonglong2* vv = (const ulonglong2*)vbuf[cur];               \
        u64 a0 = 0ull, a1 = 0ull;                                          \
        _Pragma("unroll")                                                  \
        for (int q = 0; q < 16; ++q) {                                     \
            ulonglong2 x = vv[q];                                          \
            a0 = fma2(Et2[2 * q],     x.x, a0);                            \
            a1 = fma2(Et2[2 * q + 1], x.y, a1);                            \
        }                                                                  \
        float w = sum2(add2(a0, a1)) * __expf(EM);                         \
        cur ^= 1;                                                          \
        vbuf[cur][i] = w;                                                  \
        __syncthreads();                                                   \
    }

    // step + power-of-2 rescale (consistent across threads: max over shared v)
#define STEP_RESCALE(EM)                                                   \
    {                                                                      \
        const float4* vf = (const float4*)vbuf[cur];                       \
        u64 a0 = 0ull, a1 = 0ull;                                          \
        float mx = 0.0f;                                                   \
        _Pragma("unroll")                                                  \
        for (int q = 0; q < 16; ++q) {                                     \
            float4 y = vf[q];                                              \
            a0 = fma2(Et2[2 * q],     pack2(y.x, y.y), a0);                \
            a1 = fma2(Et2[2 * q + 1], pack2(y.z, y.w), a1);                \
            mx = fmaxf(mx, fmaxf(fmaxf(y.x, y.y), fmaxf(y.z, y.w)));       \
        }                                                                  \
        float w = sum2(add2(a0, a1)) * __expf(EM);                         \
        if (mx > 0.0f) {                                                   \
            int k = ((__float_as_int(mx) >> 23) & 0xFF) - 127;             \
            ktot += k;                                                     \
            w *= __int_as_float((127 - k) << 23);                          \
        }                                                                  \
        cur ^= 1;                                                          \
        vbuf[cur][i] = w;                                                  \
        __syncthreads();                                                   \
    }

    for (int t0 = 0; t0 < len4; t0 += 4) {
        // prefetch group t0+8 (feats rows always exist up to T-1; values
        // past len are never consumed)
        int p = t0 + 8;
        float g0 = 0.f, g1 = 0.f, g2 = 0.f, g3 = 0.f;
        if (p < T_) {
            g0 = fb[(p + 0) * K_ + i];
            g1 = fb[(p + 1) * K_ + i];
            g2 = fb[(p + 2) * K_ + i];
            g3 = fb[(p + 3) * K_ + i];
        }

        STEP_PACKED(e0);
        STEP_PACKED(e1);
        STEP_PACKED(e2);
        STEP_RESCALE(e3);

        e0 = f0; e1 = f1; e2 = f2; e3 = f3;
        f0 = g0; f1 = g1; f2 = g2; f3 = g3;
    }

    // remainder (0-3 steps), emissions already in e0..e2; no rescale needed
    const int rem = len - len4;
    if (rem > 0) STEP_PACKED(e0);
    if (rem > 1) STEP_PACKED(e1);
    if (rem > 2) STEP_PACKED(e2);

    // ---- terminal: fwd = ktot*ln2 + log( sum_i v[i]*exp(trans[STOP,i]) ) ----
    float u = vbuf[cur][i] * EtStop;
#pragma unroll
    for (int off = 16; off; off >>= 1) {
        u    += __shfl_xor_sync(0xFFFFFFFFu, u,    off);
        gold += __shfl_xor_sync(0xFFFFFFFFu, gold, off);
    }
    if ((i & 31) == 0) { partu[i >> 5] = u; partg[i >> 5] = gold; }
    __syncthreads();
    if (i == 0) {
        float fwd = (float)((double)ktot * 0.69314718055994530942)
                  + logf(partu[0] + partu[1]);
        atomicAdd(out, (fwd - (partg[0] + partg[1])) * (1.0f / (float)B_));
    }
#undef STEP_PACKED
#undef STEP_RESCALE
}

extern "C" void kernel_launch(void* const* d_in, const int* in_sizes, int n_in,
                              void* d_out, int out_size)
{
    const float* feats   = (const float*)d_in[0];
    const int*   lengths = (const int*)  d_in[1];
    const int*   tags    = (const int*)  d_in[2];
    const float* trans   = (const float*)d_in[3];
    float* out = (float*)d_out;

    crf_zero_kernel<<<1, 1>>>(out);
    crf_fwd_kernel<<<B_, 64>>>(feats, lengths, tags, trans, out);
}